// round 16
// baseline (speedup 1.0000x reference)
#include <cuda_runtime.h>
#include <cuda_bf16.h>
#include <math.h>
#include <stdint.h>

#define MAXN 50000
#define MAXE 800000
#define MAXET (MAXE + MAXN)

// ---------------- static scratch (no allocation allowed) ----------------
__device__ float g_h0[MAXN * 128];     // encoder output
__device__ float g_h1[MAXN * 128];     // layer1 output
__device__ float g_h2[MAXN * 128];     // layer2 output
__device__ float g_xlr[MAXN * 256];    // xl | xr, row stride 256
__device__ float g_denom1[MAXN * 4];   // layer1 softmax denominators
__device__ float g_denom2[MAXN * 4];   // layer2 softmax denominators
__device__ int   g_deg[MAXN];
__device__ int   g_rowptr[MAXN + 1];
__device__ int   g_cursor[MAXN];
__device__ int   g_bsum[64];
__device__ int2  g_csr[MAXET];         // (src, eid) packed
__device__ float g_alpha_fb[MAXET * 4];
// bf16-split transposed weights: [set][n*128+k]; sets 0,1 are 256-wide, set 2 is 128-wide
__device__ __nv_bfloat16 g_bhi[3][256 * 128];
__device__ __nv_bfloat16 g_blo[3][256 * 128];

// ---------------- HMMA helper (sm_80 PTX, valid under compute_103) ----------------
__device__ __forceinline__ void mma16816(float* d, const uint32_t* a, const uint32_t* b) {
    asm volatile(
        "mma.sync.aligned.m16n8k16.row.col.f32.bf16.bf16.f32 "
        "{%0,%1,%2,%3}, {%4,%5,%6,%7}, {%8,%9}, {%0,%1,%2,%3};"
        : "+f"(d[0]), "+f"(d[1]), "+f"(d[2]), "+f"(d[3])
        : "r"(a[0]), "r"(a[1]), "r"(a[2]), "r"(a[3]), "r"(b[0]), "r"(b[1]));
}

// ---------------- CSR construction ----------------
__global__ void build_deg(const int* __restrict__ ei, int E, int Etot) {
    int e = blockIdx.x * blockDim.x + threadIdx.x;
    if (e >= Etot) return;
    int dst = (e < E) ? ei[E + e] : (e - E);
    atomicAdd(&g_deg[dst], 1);
}

__global__ void scan_blocks(int N) {
    __shared__ int wsum[32];
    int i = blockIdx.x * 1024 + threadIdx.x;
    int lane = threadIdx.x & 31;
    int wid  = threadIdx.x >> 5;
    int v = (i < N) ? g_deg[i] : 0;
    int x = v;
    #pragma unroll
    for (int off = 1; off < 32; off <<= 1) {
        int y = __shfl_up_sync(0xffffffffu, x, off);
        if (lane >= off) x += y;
    }
    if (lane == 31) wsum[wid] = x;
    __syncthreads();
    if (wid == 0) {
        int w = wsum[lane];
        #pragma unroll
        for (int off = 1; off < 32; off <<= 1) {
            int y = __shfl_up_sync(0xffffffffu, w, off);
            if (lane >= off) w += y;
        }
        wsum[lane] = w;
    }
    __syncthreads();
    int excl = x - v + (wid > 0 ? wsum[wid - 1] : 0);
    if (i < N) g_rowptr[i] = excl;
    if (threadIdx.x == 1023) g_bsum[blockIdx.x] = excl + v;
}

// add block offsets (each block redundantly scans <=64 block sums), init cursor,
// and write grand total to g_rowptr[N] (block 0).
__global__ void add_offsets(int N, int nb) {
    __shared__ int pref[65];
    int lane = threadIdx.x & 31;
    if (threadIdx.x < 32) {
        int v0 = (lane < nb) ? g_bsum[lane] : 0;
        int v1 = (lane + 32 < nb) ? g_bsum[lane + 32] : 0;
        int x0 = v0, x1 = v1;
        #pragma unroll
        for (int off = 1; off < 32; off <<= 1) {
            int y0 = __shfl_up_sync(0xffffffffu, x0, off);
            int y1 = __shfl_up_sync(0xffffffffu, x1, off);
            if (lane >= off) { x0 += y0; x1 += y1; }
        }
        int tot0 = __shfl_sync(0xffffffffu, x0, 31);
        int tot1 = __shfl_sync(0xffffffffu, x1, 31);
        pref[lane]      = x0 - v0;
        pref[lane + 32] = tot0 + x1 - v1;
        if (lane == 31) pref[64] = tot0 + tot1;
    }
    __syncthreads();
    int i = blockIdx.x * blockDim.x + threadIdx.x;
    if (i < N) {
        int r = g_rowptr[i] + pref[i >> 10];
        g_rowptr[i] = r;
        g_cursor[i] = r;
    }
    if (blockIdx.x == 0 && threadIdx.x == 0) g_rowptr[N] = pref[64];
}

__global__ void scatter_edges(const int* __restrict__ ei, int E, int Etot) {
    int e = blockIdx.x * blockDim.x + threadIdx.x;
    if (e >= Etot) return;
    int src, dst;
    if (e < E) { src = ei[e]; dst = ei[E + e]; }
    else       { src = dst = e - E; }
    int pos = atomicAdd(&g_cursor[dst], 1);
    g_csr[pos] = make_int2(src, e);
}

// ---------------- weight prep (all 3 sets) ----------------
__global__ void prep_all(const float* __restrict__ W0l, const float* __restrict__ W0r,
                         const float* __restrict__ W1l, const float* __restrict__ W1r,
                         const float* __restrict__ W2m) {
    const int S = 256 * 128;
    int i = blockIdx.x * blockDim.x + threadIdx.x;
    if (i >= 2 * S + 128 * 128) return;
    int set, j;
    const float *Wl, *Wr;
    if (i < S)            { set = 0; j = i;         Wl = W0l; Wr = W0r; }
    else if (i < 2 * S)   { set = 1; j = i - S;     Wl = W1l; Wr = W1r; }
    else                  { set = 2; j = i - 2 * S; Wl = W2m; Wr = W2m; }
    int n = j >> 7, k = j & 127;
    float w = (n < 128) ? Wl[k * 128 + n] : Wr[k * 128 + (n - 128)];
    __nv_bfloat16 h = __float2bfloat16(w);
    g_bhi[set][j] = h;
    g_blo[set][j] = __float2bfloat16(w - __bfloat162float(h));
}

// ---------------- encoder: h0 = x @ W(16x128) + b ----------------
__global__ void encoder_kernel(const float* __restrict__ x,
                               const float* __restrict__ W,
                               const float* __restrict__ b, int N) {
    int n = blockIdx.x;
    if (n >= N) return;
    int t = threadIdx.x;  // 128 threads
    __shared__ float xs[16];
    if (t < 16) xs[t] = x[n * 16 + t];
    __syncthreads();
    float acc = b[t];
    #pragma unroll
    for (int k = 0; k < 16; k++) acc = fmaf(xs[k], W[k * 128 + t], acc);
    g_h0[n * 128 + t] = acc;
}

// ---------------- HMMA bf16-split GEMM (k double-staged -> occupancy 2) ----------------
// C[M, gy*128 .. +128] = A[M,128](fp32) @ Bt^T + bias, via A1B1 + A2B1 + A1B2.
// B tiles staged in two k=64 halves: smem 106.5KB -> 2 CTAs/SM.
// FINAL=1: epilogue computes probs = sigmoid(relu(acc+bias) . W2 + b2) directly.
// CTA = 128 rows x 128 cols. 8 warps in 4x2 (m x n); warp tile 32x64.
#define SSTRIDE 136
#define BSTRIDE 72
#define TSTRIDE 132
template <int RELU, int FINAL>
__global__ __launch_bounds__(256, 2)
void gemm_hmma(const float* __restrict__ A,
               const __nv_bfloat16* __restrict__ Bhi,
               const __nv_bfloat16* __restrict__ Blo,
               const float* __restrict__ bias0, const float* __restrict__ bias1,
               float* __restrict__ C, int ldc, int M,
               const float* __restrict__ W2, const float* __restrict__ b2,
               float* __restrict__ probs)
{
    extern __shared__ __nv_bfloat16 smem[];
    __nv_bfloat16* As1 = smem;                     // 128 x 136 (full k)
    __nv_bfloat16* As2 = As1 + 128 * SSTRIDE;
    __nv_bfloat16* Bs1 = As2 + 128 * SSTRIDE;      // 128 x 72 (k-half)
    __nv_bfloat16* Bs2 = Bs1 + 128 * BSTRIDE;
    float* ts = (float*)smem;                      // FINAL: 128 x 132 f32 overlay (A region)

    int tid = threadIdx.x;
    int wid = tid >> 5, lane = tid & 31;
    int m0 = blockIdx.x * 128;
    int gy = blockIdx.y;
    const float* bias = gy ? bias1 : bias0;
    const __nv_bfloat16* Bh = Bhi + (size_t)gy * 128 * 128;
    const __nv_bfloat16* Bl = Blo + (size_t)gy * 128 * 128;
    float* Cg = C + gy * 128;

    // A: fp32 -> bf16 hi/lo into padded smem (full k=128)
    #pragma unroll
    for (int it = 0; it < 16; it++) {
        int j = tid + it * 256;            // 0..4095 float4s
        int r = j >> 5, c4 = (j & 31) * 4;
        int m = m0 + r;
        float4 av = (m < M) ? *(const float4*)(A + (size_t)m * 128 + c4)
                            : make_float4(0.f, 0.f, 0.f, 0.f);
        __nv_bfloat16 h[4], l[4];
        h[0] = __float2bfloat16(av.x); l[0] = __float2bfloat16(av.x - __bfloat162float(h[0]));
        h[1] = __float2bfloat16(av.y); l[1] = __float2bfloat16(av.y - __bfloat162float(h[1]));
        h[2] = __float2bfloat16(av.z); l[2] = __float2bfloat16(av.z - __bfloat162float(h[2]));
        h[3] = __float2bfloat16(av.w); l[3] = __float2bfloat16(av.w - __bfloat162float(h[3]));
        uint2 ph, pl;
        ph.x = ((uint32_t)__bfloat16_as_ushort(h[1]) << 16) | __bfloat16_as_ushort(h[0]);
        ph.y = ((uint32_t)__bfloat16_as_ushort(h[3]) << 16) | __bfloat16_as_ushort(h[2]);
        pl.x = ((uint32_t)__bfloat16_as_ushort(l[1]) << 16) | __bfloat16_as_ushort(l[0]);
        pl.y = ((uint32_t)__bfloat16_as_ushort(l[3]) << 16) | __bfloat16_as_ushort(l[2]);
        *(uint2*)(As1 + r * SSTRIDE + c4) = ph;
        *(uint2*)(As2 + r * SSTRIDE + c4) = pl;
    }

    int wm = wid >> 1;      // 0..3 -> m offset wm*32
    int wn = wid & 1;       // 0..1 -> n offset wn*64
    int lr = lane >> 2;     // 0..7
    int lc = lane & 3;      // 0..3

    float acc[2][8][4];
    #pragma unroll
    for (int mi = 0; mi < 2; mi++)
        #pragma unroll
        for (int nj = 0; nj < 8; nj++)
            #pragma unroll
            for (int q = 0; q < 4; q++) acc[mi][nj][q] = 0.f;

    const __nv_bfloat16* Apt[3] = {As1, As2, As1};
    const __nv_bfloat16* Bpt[3] = {Bs1, Bs1, Bs2};

    #pragma unroll
    for (int kh = 0; kh < 2; kh++) {
        // B k-half: bf16 [128][64] row-major -> padded smem (uint4 = 8 bf16 per iter)
        #pragma unroll
        for (int it = 0; it < 4; it++) {
            int j = tid + it * 256;        // 0..1023 uint4s
            int n = j >> 3, k8 = (j & 7) * 8;
            *(uint4*)(Bs1 + n * BSTRIDE + k8) = *(const uint4*)(Bh + (size_t)n * 128 + kh * 64 + k8);
            *(uint4*)(Bs2 + n * BSTRIDE + k8) = *(const uint4*)(Bl + (size_t)n * 128 + kh * 64 + k8);
        }
        __syncthreads();

        #pragma unroll
        for (int t = 0; t < 3; t++) {
            const __nv_bfloat16* Ap = Apt[t];
            const __nv_bfloat16* Bp = Bpt[t];
            #pragma unroll
            for (int kk = 0; kk < 4; kk++) {
                int k0a = kh * 64 + kk * 16 + lc * 2;
                int k0b = kk * 16 + lc * 2;
                uint32_t a[2][4], b[8][2];
                #pragma unroll
                for (int mi = 0; mi < 2; mi++) {
                    int m = wm * 32 + mi * 16 + lr;
                    a[mi][0] = *(const uint32_t*)(Ap + m * SSTRIDE + k0a);
                    a[mi][1] = *(const uint32_t*)(Ap + (m + 8) * SSTRIDE + k0a);
                    a[mi][2] = *(const uint32_t*)(Ap + m * SSTRIDE + k0a + 8);
                    a[mi][3] = *(const uint32_t*)(Ap + (m + 8) * SSTRIDE + k0a + 8);
                }
                #pragma unroll
                for (int nj = 0; nj < 8; nj++) {
                    int n = wn * 64 + nj * 8 + lr;
                    b[nj][0] = *(const uint32_t*)(Bp + n * BSTRIDE + k0b);
                    b[nj][1] = *(const uint32_t*)(Bp + n * BSTRIDE + k0b + 8);
                }
                #pragma unroll
                for (int mi = 0; mi < 2; mi++)
                    #pragma unroll
                    for (int nj = 0; nj < 8; nj++)
                        mma16816(acc[mi][nj], a[mi], b[nj]);
            }
        }
        __syncthreads();
    }

    if (FINAL) {
        // stage t = relu(acc + bias) into smem (overlays A region; all compute done)
        #pragma unroll
        for (int nj = 0; nj < 8; nj++) {
            int col = wn * 64 + nj * 8 + lc * 2;
            float b0 = bias[col], b1 = bias[col + 1];
            #pragma unroll
            for (int mi = 0; mi < 2; mi++) {
                int r = wm * 32 + mi * 16 + lr;
                float2 v0, v1;
                v0.x = fmaxf(acc[mi][nj][0] + b0, 0.f);
                v0.y = fmaxf(acc[mi][nj][1] + b1, 0.f);
                v1.x = fmaxf(acc[mi][nj][2] + b0, 0.f);
                v1.y = fmaxf(acc[mi][nj][3] + b1, 0.f);
                *(float2*)(ts + r * TSTRIDE + col) = v0;
                *(float2*)(ts + (r + 8) * TSTRIDE + col) = v1;
            }
        }
        __syncthreads();
        // warp wid handles rows wid*16 .. +15: deterministic shuffle dot with W2
        float w2v[4];
        #pragma unroll
        for (int j = 0; j < 4; j++) w2v[j] = W2[lane + 32 * j];
        float bb2 = b2[0];
        #pragma unroll
        for (int rr = 0; rr < 16; rr++) {
            int r = wid * 16 + rr;
            const float* row = ts + r * TSTRIDE;
            float s = row[lane] * w2v[0];
            s = fmaf(row[lane + 32],  w2v[1], s);
            s = fmaf(row[lane + 64],  w2v[2], s);
            s = fmaf(row[lane + 96],  w2v[3], s);
            #pragma unroll
            for (int off = 16; off > 0; off >>= 1)
                s += __shfl_xor_sync(0xffffffffu, s, off);
            int m = m0 + r;
            if (lane == 0 && m < M)
                probs[m] = 1.f / (1.f + __expf(-(s + bb2)));
        }
    } else {
        #pragma unroll
        for (int nj = 0; nj < 8; nj++) {
            int col = wn * 64 + nj * 8 + lc * 2;
            float b0 = bias[col], b1 = bias[col + 1];
            #pragma unroll
            for (int mi = 0; mi < 2; mi++) {
                int m = m0 + wm * 32 + mi * 16 + lr;
                float2 v0, v1;
                v0.x = acc[mi][nj][0] + b0; v0.y = acc[mi][nj][1] + b1;
                v1.x = acc[mi][nj][2] + b0; v1.y = acc[mi][nj][3] + b1;
                if (RELU) {
                    v0.x = fmaxf(v0.x, 0.f); v0.y = fmaxf(v0.y, 0.f);
                    v1.x = fmaxf(v1.x, 0.f); v1.y = fmaxf(v1.y, 0.f);
                }
                if (m < M)     *(float2*)(Cg + (size_t)m * ldc + col) = v0;
                if (m + 8 < M) *(float2*)(Cg + (size_t)(m + 8) * ldc + col) = v1;
            }
        }
    }
}

// ---------------- GATv2 aggregation: one warp per destination node ----------------
// 4-edge unrolled; per-head lanes (q==0) store their own ex scalar (no broadcasts).
__global__ void gat_aggregate(const float* __restrict__ xlr,
                              const float* __restrict__ att,  // [4*32]
                              const float* __restrict__ bo,   // [128]
                              float* __restrict__ hout,       // [N,128]
                              float* __restrict__ alpha,      // [Etot,4] (raw ex)
                              float* __restrict__ denom,      // [N,4]
                              int N, int do_relu)
{
    int warp = (blockIdx.x * blockDim.x + threadIdx.x) >> 5;
    int lane = threadIdx.x & 31;
    if (warp >= N) return;

    int h = lane >> 3;
    int q = lane & 7;
    int co = h * 32 + q * 4;

    float4 xr4 = *(const float4*)(xlr + (size_t)warp * 256 + 128 + co);
    float4 at4 = *(const float4*)(att + co);
    float4 acc = make_float4(0.f, 0.f, 0.f, 0.f);
    float  D   = 0.f;

    int beg = g_rowptr[warp], end = g_rowptr[warp + 1];
    int i = beg;
    for (; i + 4 <= end; i += 4) {
        int2 se[4];
        float4 xv[4];
        #pragma unroll
        for (int u = 0; u < 4; u++) se[u] = g_csr[i + u];
        #pragma unroll
        for (int u = 0; u < 4; u++)
            xv[u] = *(const float4*)(xlr + (size_t)se[u].x * 256 + co);
        float s[4];
        #pragma unroll
        for (int u = 0; u < 4; u++) {
            float e0 = xv[u].x + xr4.x; e0 = fmaxf(e0, 0.2f * e0);
            float e1 = xv[u].y + xr4.y; e1 = fmaxf(e1, 0.2f * e1);
            float e2 = xv[u].z + xr4.z; e2 = fmaxf(e2, 0.2f * e2);
            float e3 = xv[u].w + xr4.w; e3 = fmaxf(e3, 0.2f * e3);
            float sv = e0 * at4.x;
            sv = fmaf(e1, at4.y, sv);
            sv = fmaf(e2, at4.z, sv);
            sv = fmaf(e3, at4.w, sv);
            s[u] = sv;
        }
        #pragma unroll
        for (int off = 1; off <= 4; off <<= 1)
            #pragma unroll
            for (int u = 0; u < 4; u++)
                s[u] += __shfl_xor_sync(0xffffffffu, s[u], off);
        #pragma unroll
        for (int u = 0; u < 4; u++) {
            float ex = __expf(s[u]);           // scores << 1 -> no max-subtraction
            D += ex;
            acc.x = fmaf(ex, xv[u].x, acc.x);
            acc.y = fmaf(ex, xv[u].y, acc.y);
            acc.z = fmaf(ex, xv[u].z, acc.z);
            acc.w = fmaf(ex, xv[u].w, acc.w);
            if (q == 0) alpha[(size_t)se[u].y * 4 + h] = ex;
        }
    }
    for (; i < end; i++) {
        int2 se = g_csr[i];
        float4 xv = *(const float4*)(xlr + (size_t)se.x * 256 + co);
        float e0 = xv.x + xr4.x; e0 = fmaxf(e0, 0.2f * e0);
        float e1 = xv.y + xr4.y; e1 = fmaxf(e1, 0.2f * e1);
        float e2 = xv.z + xr4.z; e2 = fmaxf(e2, 0.2f * e2);
        float e3 = xv.w + xr4.w; e3 = fmaxf(e3, 0.2f * e3);
        float s = e0 * at4.x;
        s = fmaf(e1, at4.y, s);
        s = fmaf(e2, at4.z, s);
        s = fmaf(e3, at4.w, s);
        s += __shfl_xor_sync(0xffffffffu, s, 1);
        s += __shfl_xor_sync(0xffffffffu, s, 2);
        s += __shfl_xor_sync(0xffffffffu, s, 4);
        float ex = __expf(s);
        D += ex;
        acc.x = fmaf(ex, xv.x, acc.x);
        acc.y = fmaf(ex, xv.y, acc.y);
        acc.z = fmaf(ex, xv.z, acc.z);
        acc.w = fmaf(ex, xv.w, acc.w);
        if (q == 0) alpha[(size_t)se.y * 4 + h] = ex;
    }

    if (q == 0) denom[(size_t)warp * 4 + h] = D;
    float invD = 1.f / D;
    float4 b4 = *(const float4*)(bo + co);
    float4 o;
    o.x = acc.x * invD + b4.x;
    o.y = acc.y * invD + b4.y;
    o.z = acc.z * invD + b4.z;
    o.w = acc.w * invD + b4.w;
    if (do_relu) {
        o.x = fmaxf(o.x, 0.f); o.y = fmaxf(o.y, 0.f);
        o.z = fmaxf(o.z, 0.f); o.w = fmaxf(o.w, 0.f);
    }
    *(float4*)(hout + (size_t)warp * 128 + co) = o;
}

// normalize both layers' alphas in one streaming pass (reads ei once)
__global__ void normalize_both(const int* __restrict__ ei,
                               float* __restrict__ alpha1,
                               float* __restrict__ alpha2,
                               int E, int Etot)
{
    int e = blockIdx.x * blockDim.x + threadIdx.x;
    if (e >= Etot) return;
    int dst = (e < E) ? ei[E + e] : (e - E);
    float4 d1 = *(const float4*)(g_denom1 + (size_t)dst * 4);
    float4 d2 = *(const float4*)(g_denom2 + (size_t)dst * 4);
    float4 a1 = *(float4*)(alpha1 + (size_t)e * 4);
    float4 a2 = *(float4*)(alpha2 + (size_t)e * 4);
    a1.x /= d1.x; a1.y /= d1.y; a1.z /= d1.z; a1.w /= d1.w;
    a2.x /= d2.x; a2.y /= d2.y; a2.z /= d2.z; a2.w /= d2.w;
    *(float4*)(alpha1 + (size_t)e * 4) = a1;
    *(float4*)(alpha2 + (size_t)e * 4) = a2;
}

// ---------------- launch ----------------
extern "C" void kernel_launch(void* const* d_in, const int* in_sizes, int n_in,
                              void* d_out, int out_size)
{
    const float* x      = (const float*)d_in[0];
    const int*   ei     = (const int*)  d_in[1];
    const float* enc_W  = (const float*)d_in[4];
    const float* enc_b  = (const float*)d_in[5];
    const float* g1_Wl  = (const float*)d_in[6];
    const float* g1_bl  = (const float*)d_in[7];
    const float* g1_Wr  = (const float*)d_in[8];
    const float* g1_br  = (const float*)d_in[9];
    const float* g1_att = (const float*)d_in[10];
    const float* g1_bo  = (const float*)d_in[11];
    const float* g2_Wl  = (const float*)d_in[12];
    const float* g2_bl  = (const float*)d_in[13];
    const float* g2_Wr  = (const float*)d_in[14];
    const float* g2_br  = (const float*)d_in[15];
    const float* g2_att = (const float*)d_in[16];
    const float* g2_bo  = (const float*)d_in[17];
    const float* mlp_W1 = (const float*)d_in[18];
    const float* mlp_b1 = (const float*)d_in[19];
    const float* mlp_W2 = (const float*)d_in[20];
    const float* mlp_b2 = (const float*)d_in[21];

    int N    = in_sizes[0] / 16;
    int E    = in_sizes[1] / 2;
    int Etot = E + N;

    float *h0, *h1, *h2, *xlr, *fb, *d1p, *d2p;
    int* degp;
    __nv_bfloat16 *bhi, *blo;
    cudaGetSymbolAddress((void**)&h0,   g_h0);
    cudaGetSymbolAddress((void**)&h1,   g_h1);
    cudaGetSymbolAddress((void**)&h2,   g_h2);
    cudaGetSymbolAddress((void**)&xlr,  g_xlr);
    cudaGetSymbolAddress((void**)&fb,   g_alpha_fb);
    cudaGetSymbolAddress((void**)&d1p,  g_denom1);
    cudaGetSymbolAddress((void**)&d2p,  g_denom2);
    cudaGetSymbolAddress((void**)&degp, g_deg);
    cudaGetSymbolAddress((void**)&bhi,  g_bhi);
    cudaGetSymbolAddress((void**)&blo,  g_blo);
    const int WSTRIDE = 256 * 128;

    float* probs = (float*)d_out;
    float* alpha1;
    float* alpha2;
    if (out_size >= N + 8 * Etot) {
        alpha1 = probs + N;
        alpha2 = alpha1 + (size_t)4 * Etot;
    } else {
        alpha1 = fb;
        alpha2 = fb;
    }

    int eb = (Etot + 255) / 256;
    int nb = (N + 255) / 256;
    int wb = (N * 32 + 255) / 256;       // warp-per-node grids
    int sb = (N + 1023) / 1024;          // scan blocks (<=64)

    // smem: 2 x (128x136) A + 2 x (128x72) B halves = 106496 B -> 2 CTAs/SM
    const size_t SMEM = (2 * 128 * SSTRIDE + 2 * 128 * BSTRIDE) * sizeof(__nv_bfloat16);
    cudaFuncSetAttribute(gemm_hmma<0, 0>, cudaFuncAttributeMaxDynamicSharedMemorySize, (int)SMEM);
    cudaFuncSetAttribute(gemm_hmma<1, 1>, cudaFuncAttributeMaxDynamicSharedMemorySize, (int)SMEM);
    dim3 gg2((N + 127) / 128, 2);
    dim3 gg1((N + 127) / 128, 1);

    // one-time aux stream/events for graph fork-join (resource setup only;
    // identical work enqueued every call -> deterministic captured graph)
    static cudaStream_t s2 = 0;
    static cudaEvent_t evA = 0, evB = 0, evC = 0, evD = 0;
    if (s2 == 0) {
        cudaStreamCreateWithFlags(&s2, cudaStreamNonBlocking);
        cudaEventCreateWithFlags(&evA, cudaEventDisableTiming);
        cudaEventCreateWithFlags(&evB, cudaEventDisableTiming);
        cudaEventCreateWithFlags(&evC, cudaEventDisableTiming);
        cudaEventCreateWithFlags(&evD, cudaEventDisableTiming);
    }

    // ---- fork 1: CSR build on s2 || prep + encoder + GEMM1 on main ----
    cudaEventRecord(evA, 0);
    cudaStreamWaitEvent(s2, evA, 0);

    cudaMemsetAsync(degp, 0, (size_t)N * sizeof(int), s2);
    build_deg<<<eb, 256, 0, s2>>>(ei, E, Etot);
    scan_blocks<<<sb, 1024, 0, s2>>>(N);
    add_offsets<<<nb, 256, 0, s2>>>(N, sb);
    scatter_edges<<<eb, 256, 0, s2>>>(ei, E, Etot);
    cudaEventRecord(evB, s2);

    prep_all<<<(2 * 256 * 128 + 128 * 128 + 255) / 256, 256>>>(g1_Wl, g1_Wr, g2_Wl, g2_Wr, mlp_W1);
    encoder_kernel<<<N, 128>>>(x, enc_W, enc_b, N);
    gemm_hmma<0, 0><<<gg2, 256, SMEM>>>(h0, bhi + 0 * WSTRIDE, blo + 0 * WSTRIDE,
                                        g1_bl, g1_br, xlr, 256, N,
                                        (const float*)0, (const float*)0, (float*)0);

    // ---- join 1: aggregation needs both CSR and xlr ----
    cudaStreamWaitEvent(0, evB, 0);

    gat_aggregate<<<wb, 256>>>(xlr, g1_att, g1_bo, h1, alpha1, d1p, N, 1);

    // GAT layer 2
    gemm_hmma<0, 0><<<gg2, 256, SMEM>>>(h1, bhi + 1 * WSTRIDE, blo + 1 * WSTRIDE,
                                        g2_bl, g2_br, xlr, 256, N,
                                        (const float*)0, (const float*)0, (float*)0);
    gat_aggregate<<<wb, 256>>>(xlr, g2_att, g2_bo, h2, alpha2, d2p, N, 0);

    // ---- fork 2: normalize_both on s2 || MLP GEMM+final on main ----
    cudaEventRecord(evC, 0);
    cudaStreamWaitEvent(s2, evC, 0);
    normalize_both<<<eb, 256, 0, s2>>>(ei, alpha1, alpha2, E, Etot);
    cudaEventRecord(evD, s2);

    gemm_hmma<1, 1><<<gg1, 256, SMEM>>>(h2, bhi + 2 * WSTRIDE, blo + 2 * WSTRIDE,
                                        mlp_b1, mlp_b1, (float*)0, 128, N,
                                        mlp_W2, mlp_b2, probs);

    // ---- join 2: everything complete on the captured stream ----
    cudaStreamWaitEvent(0, evD, 0);
}

// round 17
// speedup vs baseline: 1.1118x; 1.1118x over previous
#include <cuda_runtime.h>
#include <cuda_bf16.h>
#include <math.h>
#include <stdint.h>

#define MAXN 50000
#define MAXE 800000
#define MAXET (MAXE + MAXN)

// ---------------- static scratch (no allocation allowed) ----------------
__device__ float g_h0[MAXN * 128];     // encoder output
__device__ float g_h1[MAXN * 128];     // layer1 output
__device__ float g_h2[MAXN * 128];     // layer2 output
__device__ float g_xlr[MAXN * 256];    // xl | xr, row stride 256
__device__ float g_denom1[MAXN * 4];   // layer1 softmax denominators
__device__ float g_denom2[MAXN * 4];   // layer2 softmax denominators
__device__ int   g_deg[MAXN];
__device__ int   g_rowptr[MAXN + 1];
__device__ int   g_cursor[MAXN];
__device__ int   g_bsum[64];
__device__ int2  g_csr[MAXET];         // (src, eid) packed
__device__ float g_alpha_fb[MAXET * 4];
// bf16-split transposed weights: [set][n*128+k]; sets 0,1 are 256-wide, set 2 is 128-wide
__device__ __nv_bfloat16 g_bhi[3][256 * 128];
__device__ __nv_bfloat16 g_blo[3][256 * 128];

// ---------------- HMMA helper (sm_80 PTX, valid under compute_103) ----------------
__device__ __forceinline__ void mma16816(float* d, const uint32_t* a, const uint32_t* b) {
    asm volatile(
        "mma.sync.aligned.m16n8k16.row.col.f32.bf16.bf16.f32 "
        "{%0,%1,%2,%3}, {%4,%5,%6,%7}, {%8,%9}, {%0,%1,%2,%3};"
        : "+f"(d[0]), "+f"(d[1]), "+f"(d[2]), "+f"(d[3])
        : "r"(a[0]), "r"(a[1]), "r"(a[2]), "r"(a[3]), "r"(b[0]), "r"(b[1]));
}

// ---------------- CSR construction ----------------
__global__ void build_deg(const int* __restrict__ ei, int E, int Etot) {
    int e = blockIdx.x * blockDim.x + threadIdx.x;
    if (e >= Etot) return;
    int dst = (e < E) ? ei[E + e] : (e - E);
    atomicAdd(&g_deg[dst], 1);
}

__global__ void scan_blocks(int N) {
    __shared__ int wsum[32];
    int i = blockIdx.x * 1024 + threadIdx.x;
    int lane = threadIdx.x & 31;
    int wid  = threadIdx.x >> 5;
    int v = (i < N) ? g_deg[i] : 0;
    int x = v;
    #pragma unroll
    for (int off = 1; off < 32; off <<= 1) {
        int y = __shfl_up_sync(0xffffffffu, x, off);
        if (lane >= off) x += y;
    }
    if (lane == 31) wsum[wid] = x;
    __syncthreads();
    if (wid == 0) {
        int w = wsum[lane];
        #pragma unroll
        for (int off = 1; off < 32; off <<= 1) {
            int y = __shfl_up_sync(0xffffffffu, w, off);
            if (lane >= off) w += y;
        }
        wsum[lane] = w;
    }
    __syncthreads();
    int excl = x - v + (wid > 0 ? wsum[wid - 1] : 0);
    if (i < N) g_rowptr[i] = excl;
    if (threadIdx.x == 1023) g_bsum[blockIdx.x] = excl + v;
}

// add block offsets (each block redundantly scans <=64 block sums), init cursor,
// and write grand total to g_rowptr[N] (block 0).
__global__ void add_offsets(int N, int nb) {
    __shared__ int pref[65];
    int lane = threadIdx.x & 31;
    if (threadIdx.x < 32) {
        int v0 = (lane < nb) ? g_bsum[lane] : 0;
        int v1 = (lane + 32 < nb) ? g_bsum[lane + 32] : 0;
        int x0 = v0, x1 = v1;
        #pragma unroll
        for (int off = 1; off < 32; off <<= 1) {
            int y0 = __shfl_up_sync(0xffffffffu, x0, off);
            int y1 = __shfl_up_sync(0xffffffffu, x1, off);
            if (lane >= off) { x0 += y0; x1 += y1; }
        }
        int tot0 = __shfl_sync(0xffffffffu, x0, 31);
        int tot1 = __shfl_sync(0xffffffffu, x1, 31);
        pref[lane]      = x0 - v0;
        pref[lane + 32] = tot0 + x1 - v1;
        if (lane == 31) pref[64] = tot0 + tot1;
    }
    __syncthreads();
    int i = blockIdx.x * blockDim.x + threadIdx.x;
    if (i < N) {
        int r = g_rowptr[i] + pref[i >> 10];
        g_rowptr[i] = r;
        g_cursor[i] = r;
    }
    if (blockIdx.x == 0 && threadIdx.x == 0) g_rowptr[N] = pref[64];
}

__global__ void scatter_edges(const int* __restrict__ ei, int E, int Etot) {
    int e = blockIdx.x * blockDim.x + threadIdx.x;
    if (e >= Etot) return;
    int src, dst;
    if (e < E) { src = ei[e]; dst = ei[E + e]; }
    else       { src = dst = e - E; }
    int pos = atomicAdd(&g_cursor[dst], 1);
    g_csr[pos] = make_int2(src, e);
}

// ---------------- encoder + weight prep fused (one launch) ----------------
// All blocks: h0 = x @ encW(16x128) + encb for node blockIdx.x.
// Blocks 0..639 additionally handle one 128-element slice of the bf16 weight split.
__global__ void encoder_prep(const float* __restrict__ x,
                             const float* __restrict__ encW,
                             const float* __restrict__ encb, int N,
                             const float* __restrict__ W0l, const float* __restrict__ W0r,
                             const float* __restrict__ W1l, const float* __restrict__ W1r,
                             const float* __restrict__ W2m) {
    int n = blockIdx.x;
    int t = threadIdx.x;  // 128 threads

    // weight prep slice (first 640 blocks cover 2*32768 + 16384 = 81920 elements)
    const int S = 256 * 128;
    int pi = n * 128 + t;
    if (pi < 2 * S + 128 * 128) {
        int set, j;
        const float *Wl, *Wr;
        if (pi < S)          { set = 0; j = pi;         Wl = W0l; Wr = W0r; }
        else if (pi < 2 * S) { set = 1; j = pi - S;     Wl = W1l; Wr = W1r; }
        else                 { set = 2; j = pi - 2 * S; Wl = W2m; Wr = W2m; }
        int nn = j >> 7, k = j & 127;
        float w = (nn < 128) ? Wl[k * 128 + nn] : Wr[k * 128 + (nn - 128)];
        __nv_bfloat16 h = __float2bfloat16(w);
        g_bhi[set][j] = h;
        g_blo[set][j] = __float2bfloat16(w - __bfloat162float(h));
    }

    // encoder
    if (n >= N) return;
    __shared__ float xs[16];
    if (t < 16) xs[t] = x[n * 16 + t];
    __syncthreads();
    float acc = encb[t];
    #pragma unroll
    for (int k = 0; k < 16; k++) acc = fmaf(xs[k], encW[k * 128 + t], acc);
    g_h0[n * 128 + t] = acc;
}

// ---------------- HMMA bf16-split GEMM ----------------
// C[M, gy*128 .. +128] = A[M,128](fp32) @ Bt^T + bias, via A1B1 + A2B1 + A1B2.
// FINAL=1: epilogue computes probs = sigmoid(relu(acc+bias) . W2 + b2) directly.
// CTA = 128 rows x 128 cols. 8 warps in 4x2 (m x n); warp tile 32x64.
#define SSTRIDE 136
#define TSTRIDE 132
template <int RELU, int FINAL>
__global__ __launch_bounds__(256, 1)
void gemm_hmma(const float* __restrict__ A,
               const __nv_bfloat16* __restrict__ Bhi,
               const __nv_bfloat16* __restrict__ Blo,
               const float* __restrict__ bias0, const float* __restrict__ bias1,
               float* __restrict__ C, int ldc, int M,
               const float* __restrict__ W2, const float* __restrict__ b2,
               float* __restrict__ probs)
{
    extern __shared__ __nv_bfloat16 smem[];
    __nv_bfloat16* As1 = smem;                     // 128 x 136
    __nv_bfloat16* As2 = As1 + 128 * SSTRIDE;
    __nv_bfloat16* Bs1 = As2 + 128 * SSTRIDE;
    __nv_bfloat16* Bs2 = Bs1 + 128 * SSTRIDE;
    float* ts = (float*)smem;                      // FINAL: 128 x 132 f32 overlay (A region)

    int tid = threadIdx.x;
    int wid = tid >> 5, lane = tid & 31;
    int m0 = blockIdx.x * 128;
    int gy = blockIdx.y;
    const float* bias = gy ? bias1 : bias0;
    const __nv_bfloat16* Bh = Bhi + (size_t)gy * 128 * 128;
    const __nv_bfloat16* Bl = Blo + (size_t)gy * 128 * 128;
    float* Cg = C + gy * 128;

    // A: fp32 -> bf16 hi/lo into padded smem
    #pragma unroll
    for (int it = 0; it < 16; it++) {
        int j = tid + it * 256;            // 0..4095 float4s
        int r = j >> 5, c4 = (j & 31) * 4;
        int m = m0 + r;
        float4 av = (m < M) ? *(const float4*)(A + (size_t)m * 128 + c4)
                            : make_float4(0.f, 0.f, 0.f, 0.f);
        __nv_bfloat16 h[4], l[4];
        h[0] = __float2bfloat16(av.x); l[0] = __float2bfloat16(av.x - __bfloat162float(h[0]));
        h[1] = __float2bfloat16(av.y); l[1] = __float2bfloat16(av.y - __bfloat162float(h[1]));
        h[2] = __float2bfloat16(av.z); l[2] = __float2bfloat16(av.z - __bfloat162float(h[2]));
        h[3] = __float2bfloat16(av.w); l[3] = __float2bfloat16(av.w - __bfloat162float(h[3]));
        uint2 ph, pl;
        ph.x = ((uint32_t)__bfloat16_as_ushort(h[1]) << 16) | __bfloat16_as_ushort(h[0]);
        ph.y = ((uint32_t)__bfloat16_as_ushort(h[3]) << 16) | __bfloat16_as_ushort(h[2]);
        pl.x = ((uint32_t)__bfloat16_as_ushort(l[1]) << 16) | __bfloat16_as_ushort(l[0]);
        pl.y = ((uint32_t)__bfloat16_as_ushort(l[3]) << 16) | __bfloat16_as_ushort(l[2]);
        *(uint2*)(As1 + r * SSTRIDE + c4) = ph;
        *(uint2*)(As2 + r * SSTRIDE + c4) = pl;
    }
    // B: bf16 [128][128] row-major -> padded smem (uint4 = 8 bf16 per iter)
    #pragma unroll
    for (int it = 0; it < 8; it++) {
        int j = tid + it * 256;            // 0..2047 uint4s
        int n = j >> 4, k8 = (j & 15) * 8;
        *(uint4*)(Bs1 + n * SSTRIDE + k8) = *(const uint4*)(Bh + (size_t)n * 128 + k8);
        *(uint4*)(Bs2 + n * SSTRIDE + k8) = *(const uint4*)(Bl + (size_t)n * 128 + k8);
    }
    __syncthreads();

    int wm = wid >> 1;      // 0..3 -> m offset wm*32
    int wn = wid & 1;       // 0..1 -> n offset wn*64
    int lr = lane >> 2;     // 0..7
    int lc = lane & 3;      // 0..3

    float acc[2][8][4];
    #pragma unroll
    for (int mi = 0; mi < 2; mi++)
        #pragma unroll
        for (int nj = 0; nj < 8; nj++)
            #pragma unroll
            for (int q = 0; q < 4; q++) acc[mi][nj][q] = 0.f;

    const __nv_bfloat16* Apt[3] = {As1, As2, As1};
    const __nv_bfloat16* Bpt[3] = {Bs1, Bs1, Bs2};

    #pragma unroll
    for (int t = 0; t < 3; t++) {
        const __nv_bfloat16* Ap = Apt[t];
        const __nv_bfloat16* Bp = Bpt[t];
        #pragma unroll
        for (int kk = 0; kk < 8; kk++) {
            int k0 = kk * 16 + lc * 2;
            uint32_t a[2][4], b[8][2];
            #pragma unroll
            for (int mi = 0; mi < 2; mi++) {
                int m = wm * 32 + mi * 16 + lr;
                a[mi][0] = *(const uint32_t*)(Ap + m * SSTRIDE + k0);
                a[mi][1] = *(const uint32_t*)(Ap + (m + 8) * SSTRIDE + k0);
                a[mi][2] = *(const uint32_t*)(Ap + m * SSTRIDE + k0 + 8);
                a[mi][3] = *(const uint32_t*)(Ap + (m + 8) * SSTRIDE + k0 + 8);
            }
            #pragma unroll
            for (int nj = 0; nj < 8; nj++) {
                int n = wn * 64 + nj * 8 + lr;
                b[nj][0] = *(const uint32_t*)(Bp + n * SSTRIDE + k0);
                b[nj][1] = *(const uint32_t*)(Bp + n * SSTRIDE + k0 + 8);
            }
            #pragma unroll
            for (int mi = 0; mi < 2; mi++)
                #pragma unroll
                for (int nj = 0; nj < 8; nj++)
                    mma16816(acc[mi][nj], a[mi], b[nj]);
        }
    }

    if (FINAL) {
        // stage t = relu(acc + bias) into smem (overlays A region; all compute done)
        __syncthreads();
        #pragma unroll
        for (int nj = 0; nj < 8; nj++) {
            int col = wn * 64 + nj * 8 + lc * 2;
            float b0 = bias[col], b1 = bias[col + 1];
            #pragma unroll
            for (int mi = 0; mi < 2; mi++) {
                int r = wm * 32 + mi * 16 + lr;
                float2 v0, v1;
                v0.x = fmaxf(acc[mi][nj][0] + b0, 0.f);
                v0.y = fmaxf(acc[mi][nj][1] + b1, 0.f);
                v1.x = fmaxf(acc[mi][nj][2] + b0, 0.f);
                v1.y = fmaxf(acc[mi][nj][3] + b1, 0.f);
                *(float2*)(ts + r * TSTRIDE + col) = v0;
                *(float2*)(ts + (r + 8) * TSTRIDE + col) = v1;
            }
        }
        __syncthreads();
        // warp wid handles rows wid*16 .. +15: deterministic shuffle dot with W2
        float w2v[4];
        #pragma unroll
        for (int j = 0; j < 4; j++) w2v[j] = W2[lane + 32 * j];
        float bb2 = b2[0];
        #pragma unroll
        for (int rr = 0; rr < 16; rr++) {
            int r = wid * 16 + rr;
            const float* row = ts + r * TSTRIDE;
            float s = row[lane] * w2v[0];
            s = fmaf(row[lane + 32],  w2v[1], s);
            s = fmaf(row[lane + 64],  w2v[2], s);
            s = fmaf(row[lane + 96],  w2v[3], s);
            #pragma unroll
            for (int off = 16; off > 0; off >>= 1)
                s += __shfl_xor_sync(0xffffffffu, s, off);
            int m = m0 + r;
            if (lane == 0 && m < M)
                probs[m] = 1.f / (1.f + __expf(-(s + bb2)));
        }
    } else {
        #pragma unroll
        for (int nj = 0; nj < 8; nj++) {
            int col = wn * 64 + nj * 8 + lc * 2;
            float b0 = bias[col], b1 = bias[col + 1];
            #pragma unroll
            for (int mi = 0; mi < 2; mi++) {
                int m = m0 + wm * 32 + mi * 16 + lr;
                float2 v0, v1;
                v0.x = acc[mi][nj][0] + b0; v0.y = acc[mi][nj][1] + b1;
                v1.x = acc[mi][nj][2] + b0; v1.y = acc[mi][nj][3] + b1;
                if (RELU) {
                    v0.x = fmaxf(v0.x, 0.f); v0.y = fmaxf(v0.y, 0.f);
                    v1.x = fmaxf(v1.x, 0.f); v1.y = fmaxf(v1.y, 0.f);
                }
                if (m < M)     *(float2*)(Cg + (size_t)m * ldc + col) = v0;
                if (m + 8 < M) *(float2*)(Cg + (size_t)(m + 8) * ldc + col) = v1;
            }
        }
    }
}

// ---------------- GATv2 aggregation: one warp per destination node ----------------
// 4-edge unrolled; per-head lanes (q==0) store their own ex scalar (no broadcasts).
__global__ void gat_aggregate(const float* __restrict__ xlr,
                              const float* __restrict__ att,  // [4*32]
                              const float* __restrict__ bo,   // [128]
                              float* __restrict__ hout,       // [N,128]
                              float* __restrict__ alpha,      // [Etot,4] (raw ex)
                              float* __restrict__ denom,      // [N,4]
                              int N, int do_relu)
{
    int warp = (blockIdx.x * blockDim.x + threadIdx.x) >> 5;
    int lane = threadIdx.x & 31;
    if (warp >= N) return;

    int h = lane >> 3;
    int q = lane & 7;
    int co = h * 32 + q * 4;

    float4 xr4 = *(const float4*)(xlr + (size_t)warp * 256 + 128 + co);
    float4 at4 = *(const float4*)(att + co);
    float4 acc = make_float4(0.f, 0.f, 0.f, 0.f);
    float  D   = 0.f;

    int beg = g_rowptr[warp], end = g_rowptr[warp + 1];
    int i = beg;
    for (; i + 4 <= end; i += 4) {
        int2 se[4];
        float4 xv[4];
        #pragma unroll
        for (int u = 0; u < 4; u++) se[u] = g_csr[i + u];
        #pragma unroll
        for (int u = 0; u < 4; u++)
            xv[u] = *(const float4*)(xlr + (size_t)se[u].x * 256 + co);
        float s[4];
        #pragma unroll
        for (int u = 0; u < 4; u++) {
            float e0 = xv[u].x + xr4.x; e0 = fmaxf(e0, 0.2f * e0);
            float e1 = xv[u].y + xr4.y; e1 = fmaxf(e1, 0.2f * e1);
            float e2 = xv[u].z + xr4.z; e2 = fmaxf(e2, 0.2f * e2);
            float e3 = xv[u].w + xr4.w; e3 = fmaxf(e3, 0.2f * e3);
            float sv = e0 * at4.x;
            sv = fmaf(e1, at4.y, sv);
            sv = fmaf(e2, at4.z, sv);
            sv = fmaf(e3, at4.w, sv);
            s[u] = sv;
        }
        #pragma unroll
        for (int off = 1; off <= 4; off <<= 1)
            #pragma unroll
            for (int u = 0; u < 4; u++)
                s[u] += __shfl_xor_sync(0xffffffffu, s[u], off);
        #pragma unroll
        for (int u = 0; u < 4; u++) {
            float ex = __expf(s[u]);           // scores << 1 -> no max-subtraction
            D += ex;
            acc.x = fmaf(ex, xv[u].x, acc.x);
            acc.y = fmaf(ex, xv[u].y, acc.y);
            acc.z = fmaf(ex, xv[u].z, acc.z);
            acc.w = fmaf(ex, xv[u].w, acc.w);
            if (q == 0) alpha[(size_t)se[u].y * 4 + h] = ex;
        }
    }
    for (; i < end; i++) {
        int2 se = g_csr[i];
        float4 xv = *(const float4*)(xlr + (size_t)se.x * 256 + co);
        float e0 = xv.x + xr4.x; e0 = fmaxf(e0, 0.2f * e0);
        float e1 = xv.y + xr4.y; e1 = fmaxf(e1, 0.2f * e1);
        float e2 = xv.z + xr4.z; e2 = fmaxf(e2, 0.2f * e2);
        float e3 = xv.w + xr4.w; e3 = fmaxf(e3, 0.2f * e3);
        float s = e0 * at4.x;
        s = fmaf(e1, at4.y, s);
        s = fmaf(e2, at4.z, s);
        s = fmaf(e3, at4.w, s);
        s += __shfl_xor_sync(0xffffffffu, s, 1);
        s += __shfl_xor_sync(0xffffffffu, s, 2);
        s += __shfl_xor_sync(0xffffffffu, s, 4);
        float ex = __expf(s);
        D += ex;
        acc.x = fmaf(ex, xv.x, acc.x);
        acc.y = fmaf(ex, xv.y, acc.y);
        acc.z = fmaf(ex, xv.z, acc.z);
        acc.w = fmaf(ex, xv.w, acc.w);
        if (q == 0) alpha[(size_t)se.y * 4 + h] = ex;
    }

    if (q == 0) denom[(size_t)warp * 4 + h] = D;
    float invD = 1.f / D;
    float4 b4 = *(const float4*)(bo + co);
    float4 o;
    o.x = acc.x * invD + b4.x;
    o.y = acc.y * invD + b4.y;
    o.z = acc.z * invD + b4.z;
    o.w = acc.w * invD + b4.w;
    if (do_relu) {
        o.x = fmaxf(o.x, 0.f); o.y = fmaxf(o.y, 0.f);
        o.z = fmaxf(o.z, 0.f); o.w = fmaxf(o.w, 0.f);
    }
    *(float4*)(hout + (size_t)warp * 128 + co) = o;
}

// normalize both layers' alphas in one streaming pass (reads ei once)
__global__ void normalize_both(const int* __restrict__ ei,
                               float* __restrict__ alpha1,
                               float* __restrict__ alpha2,
                               int E, int Etot)
{
    int e = blockIdx.x * blockDim.x + threadIdx.x;
    if (e >= Etot) return;
    int dst = (e < E) ? ei[E + e] : (e - E);
    float4 d1 = *(const float4*)(g_denom1 + (size_t)dst * 4);
    float4 d2 = *(const float4*)(g_denom2 + (size_t)dst * 4);
    float4 a1 = *(float4*)(alpha1 + (size_t)e * 4);
    float4 a2 = *(float4*)(alpha2 + (size_t)e * 4);
    a1.x /= d1.x; a1.y /= d1.y; a1.z /= d1.z; a1.w /= d1.w;
    a2.x /= d2.x; a2.y /= d2.y; a2.z /= d2.z; a2.w /= d2.w;
    *(float4*)(alpha1 + (size_t)e * 4) = a1;
    *(float4*)(alpha2 + (size_t)e * 4) = a2;
}

// ---------------- launch ----------------
extern "C" void kernel_launch(void* const* d_in, const int* in_sizes, int n_in,
                              void* d_out, int out_size)
{
    const float* x      = (const float*)d_in[0];
    const int*   ei     = (const int*)  d_in[1];
    const float* enc_W  = (const float*)d_in[4];
    const float* enc_b  = (const float*)d_in[5];
    const float* g1_Wl  = (const float*)d_in[6];
    const float* g1_bl  = (const float*)d_in[7];
    const float* g1_Wr  = (const float*)d_in[8];
    const float* g1_br  = (const float*)d_in[9];
    const float* g1_att = (const float*)d_in[10];
    const float* g1_bo  = (const float*)d_in[11];
    const float* g2_Wl  = (const float*)d_in[12];
    const float* g2_bl  = (const float*)d_in[13];
    const float* g2_Wr  = (const float*)d_in[14];
    const float* g2_br  = (const float*)d_in[15];
    const float* g2_att = (const float*)d_in[16];
    const float* g2_bo  = (const float*)d_in[17];
    const float* mlp_W1 = (const float*)d_in[18];
    const float* mlp_b1 = (const float*)d_in[19];
    const float* mlp_W2 = (const float*)d_in[20];
    const float* mlp_b2 = (const float*)d_in[21];

    int N    = in_sizes[0] / 16;
    int E    = in_sizes[1] / 2;
    int Etot = E + N;

    float *h0, *h1, *h2, *xlr, *fb, *d1p, *d2p;
    int* degp;
    __nv_bfloat16 *bhi, *blo;
    cudaGetSymbolAddress((void**)&h0,   g_h0);
    cudaGetSymbolAddress((void**)&h1,   g_h1);
    cudaGetSymbolAddress((void**)&h2,   g_h2);
    cudaGetSymbolAddress((void**)&xlr,  g_xlr);
    cudaGetSymbolAddress((void**)&fb,   g_alpha_fb);
    cudaGetSymbolAddress((void**)&d1p,  g_denom1);
    cudaGetSymbolAddress((void**)&d2p,  g_denom2);
    cudaGetSymbolAddress((void**)&degp, g_deg);
    cudaGetSymbolAddress((void**)&bhi,  g_bhi);
    cudaGetSymbolAddress((void**)&blo,  g_blo);
    const int WSTRIDE = 256 * 128;

    float* probs = (float*)d_out;
    float* alpha1;
    float* alpha2;
    if (out_size >= N + 8 * Etot) {
        alpha1 = probs + N;
        alpha2 = alpha1 + (size_t)4 * Etot;
    } else {
        alpha1 = fb;
        alpha2 = fb;
    }

    int eb = (Etot + 255) / 256;
    int nb = (N + 255) / 256;
    int wb = (N * 32 + 255) / 256;       // warp-per-node grids
    int sb = (N + 1023) / 1024;          // scan blocks (<=64)

    const size_t SMEM = 4 * 128 * SSTRIDE * sizeof(__nv_bfloat16);  // 139264 B
    cudaFuncSetAttribute(gemm_hmma<0, 0>, cudaFuncAttributeMaxDynamicSharedMemorySize, (int)SMEM);
    cudaFuncSetAttribute(gemm_hmma<1, 1>, cudaFuncAttributeMaxDynamicSharedMemorySize, (int)SMEM);
    dim3 gg2((N + 127) / 128, 2);
    dim3 gg1((N + 127) / 128, 1);

    // one-time aux stream/events for graph fork-join (resource setup only;
    // identical work enqueued every call -> deterministic captured graph)
    static cudaStream_t s2 = 0;
    static cudaEvent_t evA = 0, evB = 0, evC = 0, evD = 0;
    if (s2 == 0) {
        cudaStreamCreateWithFlags(&s2, cudaStreamNonBlocking);
        cudaEventCreateWithFlags(&evA, cudaEventDisableTiming);
        cudaEventCreateWithFlags(&evB, cudaEventDisableTiming);
        cudaEventCreateWithFlags(&evC, cudaEventDisableTiming);
        cudaEventCreateWithFlags(&evD, cudaEventDisableTiming);
    }

    // ---- fork 1: CSR build on s2 || encoder+prep + GEMM1 on main ----
    cudaEventRecord(evA, 0);
    cudaStreamWaitEvent(s2, evA, 0);

    cudaMemsetAsync(degp, 0, (size_t)N * sizeof(int), s2);
    build_deg<<<eb, 256, 0, s2>>>(ei, E, Etot);
    scan_blocks<<<sb, 1024, 0, s2>>>(N);
    add_offsets<<<nb, 256, 0, s2>>>(N, sb);
    scatter_edges<<<eb, 256, 0, s2>>>(ei, E, Etot);
    cudaEventRecord(evB, s2);

    encoder_prep<<<N, 128>>>(x, enc_W, enc_b, N,
                             g1_Wl, g1_Wr, g2_Wl, g2_Wr, mlp_W1);
    gemm_hmma<0, 0><<<gg2, 256, SMEM>>>(h0, bhi + 0 * WSTRIDE, blo + 0 * WSTRIDE,
                                        g1_bl, g1_br, xlr, 256, N,
                                        (const float*)0, (const float*)0, (float*)0);

    // ---- join 1: aggregation needs both CSR and xlr ----
    cudaStreamWaitEvent(0, evB, 0);

    gat_aggregate<<<wb, 256>>>(xlr, g1_att, g1_bo, h1, alpha1, d1p, N, 1);

    // GAT layer 2
    gemm_hmma<0, 0><<<gg2, 256, SMEM>>>(h1, bhi + 1 * WSTRIDE, blo + 1 * WSTRIDE,
                                        g2_bl, g2_br, xlr, 256, N,
                                        (const float*)0, (const float*)0, (float*)0);
    gat_aggregate<<<wb, 256>>>(xlr, g2_att, g2_bo, h2, alpha2, d2p, N, 0);

    // ---- fork 2: normalize_both on s2 || MLP GEMM+final on main ----
    cudaEventRecord(evC, 0);
    cudaStreamWaitEvent(s2, evC, 0);
    normalize_both<<<eb, 256, 0, s2>>>(ei, alpha1, alpha2, E, Etot);
    cudaEventRecord(evD, s2);

    gemm_hmma<1, 1><<<gg1, 256, SMEM>>>(h2, bhi + 2 * WSTRIDE, blo + 2 * WSTRIDE,
                                        mlp_b1, mlp_b1, (float*)0, 128, N,
                                        mlp_W2, mlp_b2, probs);

    // ---- join 2: everything complete on the captured stream ----
    cudaStreamWaitEvent(0, evD, 0);
}